// round 15
// baseline (speedup 1.0000x reference)
#include <cuda_runtime.h>
#include <cuda_fp16.h>
#include <cstdint>

// ---------------------------------------------------------------------------
// CentralCritic, both GEMMs on fp16 mma.sync.m16n8k16 (f32 accumulate).
// R15 = R14 with the serial prologue dissolved into the critic:
//   - acs fp32->fp16 conversion happens in critic's stage_buf0 (LDG+cvt+STS),
//     g_acsh eliminated (19MB off the enc critical path, re-reads hit L2)
//   - d_out zeroing is per-CTA local in the critic (rows are CTA-disjoint)
//   - enc kernel does only the enc GEMM (state -> g_ench)
// ---------------------------------------------------------------------------

#define A_   4
#define H_   3
#define HI_  2
#define C_   16
#define S_   256
#define D_   128
#define IN_  176
#define NPAIR 20
#define NCTA  296    // critic CTAs: exactly 1 resident wave (2 CTAs/SM x 148)
#define NTE   2      // 64-row tiles per enc CTA -> 256 enc CTAs

// critic smem layout (u32 offsets)
#define WP_OFF   0                       // 88 k2-rows * 136 u32 = 11968
#define X0_OFF   11968                   // 128*52 u32 = 6656
#define X1_OFF   18624                   // 128*44 u32 = 5632
#define W2_OFF   24256                   // 128*17 = 2176
#define B1_OFF   26432                   // 128
#define B2_OFF   26560                   // 16
#define K_SMEMB  (26704 * 4)             // 106816 B (x2 CTA <= 228KB)

// enc smem layout (u32 offsets)
#define EW_OFF   0                       // 128 k2-rows * 136 u32 = 17408
#define EX_OFF   17408                   // 64 rows * 132 u32 = 8448
#define EB_OFF   25856                   // 128 floats
#define E_SMEMB  (25984 * 4)             // 103936 B (x2 CTA <= 228KB)

__device__ __half g_ench[32768 * D_];    // enc activations, fp16

__constant__ int c_loo[4][3] = {{1,2,3},{0,2,3},{0,1,3},{0,1,2}};

// ---- helpers ---------------------------------------------------------------
__device__ __forceinline__ uint32_t smem_u32(const void* p) {
    uint32_t r;
    asm("{ .reg .u64 t; cvta.to.shared.u64 t, %1; cvt.u32.u64 %0, t; }"
        : "=r"(r) : "l"(p));
    return r;
}
__device__ __forceinline__ void cpasync16(uint32_t dst, const void* src) {
    asm volatile("cp.async.cg.shared.global [%0], [%1], 16;"
                 :: "r"(dst), "l"(src));
}
#define CPCOMMIT()  asm volatile("cp.async.commit_group;" ::: "memory")
#define CPWAITG(n)  asm volatile("cp.async.wait_group %0;" :: "n"(n) : "memory")

__device__ __forceinline__ void ldsm_x4(uint32_t& r0, uint32_t& r1,
                                        uint32_t& r2, uint32_t& r3,
                                        uint32_t addr) {
    asm volatile("ldmatrix.sync.aligned.m8n8.x4.shared.b16 {%0,%1,%2,%3}, [%4];"
                 : "=r"(r0), "=r"(r1), "=r"(r2), "=r"(r3) : "r"(addr));
}
// fp16 k16
__device__ __forceinline__ void mma16(float* d, const uint32_t* a,
                                      uint32_t b0, uint32_t b1) {
    asm volatile(
        "mma.sync.aligned.m16n8k16.row.col.f32.f16.f16.f32 "
        "{%0,%1,%2,%3}, {%4,%5,%6,%7}, {%8,%9}, {%0,%1,%2,%3};"
        : "+f"(d[0]), "+f"(d[1]), "+f"(d[2]), "+f"(d[3])
        : "r"(a[0]), "r"(a[1]), "r"(a[2]), "r"(a[3]), "r"(b0), "r"(b1));
}
__device__ __forceinline__ uint2 cvt4h(float4 v) {
    __half2 h0 = __floats2half2_rn(v.x, v.y);
    __half2 h1 = __floats2half2_rn(v.z, v.w);
    uint2 o; o.x = *(uint32_t*)&h0; o.y = *(uint32_t*)&h1;
    return o;
}

// ---------------------------------------------------------------------------
// encoder: relu(state @ encW + b) -> g_ench (fp16), fp16 m16n8k16 GEMM.
// 256 thr, 8 warps (4 wm x 2 wn), warp tile 16x64, 2 CTAs/SM, 2 tiles/CTA.
// ---------------------------------------------------------------------------
__global__ __launch_bounds__(256, 2) void enc_kernel(
    const float* __restrict__ state, const float* __restrict__ encW,
    const float* __restrict__ encb, int B)
{
    extern __shared__ float smf[];
    const int tid = threadIdx.x, wid = tid >> 5, lane = tid & 31;
    const int g = lane >> 2, t = lane & 3;
    const int wm = wid >> 1, wn = wid & 1;
    const int wr = wm * 16, wc = wn * 64;

    // ---- stage encW fp16, (n, n+8)-interleaved u64 rows ----
    __half* Wph = (__half*)(smf + EW_OFF);
    for (int it = 0; it < 32; it++) {
        int fi = it * 256 + tid;            // 8192 float4 (256 k x 32 n4)
        int k = fi >> 5, n0 = (fi & 31) * 4;
        float4 v = *(const float4*)(encW + (size_t)k * D_ + n0);
        int base = (k >> 1) * 272 + (n0 >> 4) * 32 + ((n0 >> 3) & 1) * 2
                 + (k & 1) + (n0 & 7) * 4;
        Wph[base + 0]  = __float2half_rn(v.x);
        Wph[base + 4]  = __float2half_rn(v.y);
        Wph[base + 8]  = __float2half_rn(v.z);
        Wph[base + 12] = __float2half_rn(v.w);
    }
    if (tid < D_) smf[EB_OFF + tid] = encb[tid];
    __syncthreads();

    const uint32_t xb = smem_u32(smf + EX_OFF);
    const uint2* Wq = (const uint2*)(smf + EW_OFF);
    const int nb = wn * 32 + g;                        // u64 col base
    const int lrow = ((lane >> 3) & 1) * 8 + (lane & 7);
    const uint32_t lk16 = (uint32_t)(lane >> 4) * 16;
    const uint32_t aXbase = xb + (uint32_t)((wr + lrow) * 528) + lk16;

    for (int tt = 0; tt < NTE; tt++) {
        const int row0 = (blockIdx.x * NTE + tt) * 64;

        // ---- stage X: 64 rows x 256 fp32 -> fp16, row stride 132 u32 ----
        uint32_t* Xu = (uint32_t*)(smf + EX_OFF);
        for (int it = 0; it < 16; it++) {
            int idx = it * 256 + tid;       // 4096 float4 positions
            int row = idx >> 6, c0 = idx & 63;
            float4 v = *(const float4*)(state + (size_t)(row0 + row) * S_ + c0 * 4);
            *(uint2*)(Xu + row * 132 + c0 * 2) = cvt4h(v);
        }
        __syncthreads();

        float acc[8][4];
#pragma unroll
        for (int ni = 0; ni < 8; ni++)
#pragma unroll
            for (int e = 0; e < 4; e++) acc[ni][e] = 0.f;

#pragma unroll
        for (int ks = 0; ks < 16; ks++) {
            uint32_t a[4];
            ldsm_x4(a[0], a[1], a[2], a[3], aXbase + ks * 32);
            const int kr0 = (ks * 8 + t) * 68 + nb;
            uint2 c0v[4], c1v[4];
#pragma unroll
            for (int j = 0; j < 4; j++) {
                c0v[j] = Wq[kr0 + j * 8];
                c1v[j] = Wq[kr0 + 4 * 68 + j * 8];
            }
#pragma unroll
            for (int j = 0; j < 4; j++) {
                mma16(acc[2 * j],     a, c0v[j].x, c1v[j].x);
                mma16(acc[2 * j + 1], a, c0v[j].y, c1v[j].y);
            }
        }
        __syncthreads();   // X consumed before next tile restage

        // ---- epilogue: bias + relu -> g_ench fp16 ----
        int r0 = row0 + wr + g;
#pragma unroll
        for (int ni = 0; ni < 8; ni++) {
            int col = wc + ni * 8 + 2 * t;
            float b0 = smf[EB_OFF + col], b1v = smf[EB_OFF + col + 1];
            __half2 h0 = __floats2half2_rn(fmaxf(acc[ni][0] + b0, 0.f),
                                           fmaxf(acc[ni][1] + b1v, 0.f));
            __half2 h1 = __floats2half2_rn(fmaxf(acc[ni][2] + b0, 0.f),
                                           fmaxf(acc[ni][3] + b1v, 0.f));
            *(__half2*)(g_ench + (size_t)r0 * D_ + col) = h0;
            *(__half2*)(g_ench + (size_t)(r0 + 8) * D_ + col) = h1;
        }
    }
}

// ---------------------------------------------------------------------------
// critic: 256 thr, 8 warps (4 wm x 2 wn), warp tile 32x64, fp16 m16n8k16,
// 2 CTAs/SM (single resident wave), ldmatrix A-feeds, u64-interleaved W,
// per-warp shfl argmax, atomic 2-partial epilogue (rows zeroed locally),
// acs staged fp32->fp16 directly into SMEM (no g_acsh).
// ---------------------------------------------------------------------------
__global__ __launch_bounds__(256, 2) void critic_kernel(
    const float* __restrict__ acs,
    const float* __restrict__ eW1, const float* __restrict__ eb1,
    const float* __restrict__ eW2, const float* __restrict__ eb2,
    const float* __restrict__ iW1, const float* __restrict__ ib1,
    const float* __restrict__ iW2, const float* __restrict__ ib2,
    float* __restrict__ out, int B)
{
    extern __shared__ float smf[];
    const int tid = threadIdx.x, wid = tid >> 5, lane = tid & 31;
    const int g = lane >> 2, t = lane & 3;
    const int wm = wid >> 1, wn = wid & 1;
    const int wr = wm * 32, wc = wn * 64;

    // ---- balanced partition over 296 CTAs / 20 pairs ----
    const int cb = blockIdx.x;                     // 0..NCTA-1
    const int p  = (cb * 5) / 74;                  // = cb*NPAIR/NCTA
    const int c0 = (74 * p + 4) / 5;               // first CTA of pair p
    const int c1 = (74 * (p + 1) + 4) / 5;         // first CTA of pair p+1
    const int cnt = c1 - c0;
    const int l = cb - c0;
    const int tilesT = B / 128;
    const int tb = (l * tilesT) / cnt;
    const int te = ((l + 1) * tilesT) / cnt;

    int i, head;
    const float *W1, *b1, *W2, *b2;
    float* outp;
    if (p < A_ * H_) {
        i = p / H_; int j = p % H_; head = j;
        W1 = eW1 + (size_t)(j * A_ + i) * IN_ * D_;
        b1 = eb1 + (size_t)(j * A_ + i) * D_;
        W2 = eW2 + (size_t)(j * A_ + i) * D_ * C_;
        b2 = eb2 + (size_t)(j * A_ + i) * C_;
        outp = out + (size_t)p * B;
    } else {
        int q = p - A_ * H_;
        i = q / HI_; int j = q % HI_; head = j + 1;
        W1 = iW1 + (size_t)(j * A_ + i) * IN_ * D_;
        b1 = ib1 + (size_t)(j * A_ + i) * D_;
        W2 = iW2 + (size_t)(j * A_ + i) * D_ * C_;
        b2 = ib2 + (size_t)(j * A_ + i) * C_;
        outp = out + (size_t)(A_ * H_) * B + (size_t)q * B;
    }
    const float* acsA32[3];
    acsA32[0] = acs + (size_t)(c_loo[i][0] * H_ + head) * B * C_;
    acsA32[1] = acs + (size_t)(c_loo[i][1] * H_ + head) * B * C_;
    acsA32[2] = acs + (size_t)(c_loo[i][2] * H_ + head) * B * C_;
    const float* acsSelf = acs + (size_t)(i * H_ + head) * B * C_;

    // ---- zero own output rows (atomic targets; CTA-disjoint) ----
    for (int r = tb * 128 + tid; r < te * 128; r += 256) outp[r] = 0.f;

    // ---- stage W1 fp16, (n, n+8)-interleaved u64 rows, k-pairs in u32 ----
    __half* Wph = (__half*)(smf + WP_OFF);
    for (int it = 0; it < 22; it++) {
        int fi = it * 256 + tid;            // 5632 float4
        int k = fi >> 5, n0 = (fi & 31) * 4;
        float4 v = *(const float4*)(W1 + (size_t)k * D_ + n0);
        int base = (k >> 1) * 272 + (n0 >> 4) * 32 + ((n0 >> 3) & 1) * 2
                 + (k & 1) + (n0 & 7) * 4;
        Wph[base + 0]  = __float2half_rn(v.x);
        Wph[base + 4]  = __float2half_rn(v.y);
        Wph[base + 8]  = __float2half_rn(v.z);
        Wph[base + 12] = __float2half_rn(v.w);
    }
    for (int it = 0; it < 8; it++) {
        int idx = it * 256 + tid;           // 2048 floats
        int d = idx >> 4, c = idx & 15;
        smf[W2_OFF + d * 17 + c] = W2[idx];
    }
    if (tid < D_) smf[B1_OFF + tid] = b1[tid];
    if (tid < C_) smf[B2_OFF + tid] = b2[tid];

    const uint32_t x0b = smem_u32(smf + X0_OFF);
    const uint32_t x1b = smem_u32(smf + X1_OFF);
    uint32_t* X0w = (uint32_t*)(smf) + X0_OFF;

    // buf0: enc[0..47] via cp.async (u32 cols 24..47) + acs fp32->fp16 via
    // LDG/cvt/STS (u32 cols 0..23).
    auto stage_buf0 = [&](int row0) {
#pragma unroll
        for (int it = 0; it < 3; it++) {
            int idx = it * 256 + tid;       // 768 chunks (6/row)
            int row = idx / 6, c = idx - (idx / 6) * 6;
            const void* src = g_ench + (size_t)(row0 + row) * D_ + c * 8;
            cpasync16(x0b + (uint32_t)(row * 52 + 24 + c * 4) * 4, src);
        }
        CPCOMMIT();
#pragma unroll
        for (int it = 0; it < 6; it++) {
            int idx = it * 256 + tid;       // 1536 items (12/row)
            int row = idx / 12, c = idx - (idx / 12) * 12;
            int a = c >> 2, c4 = c & 3;
            float4 v = *(const float4*)(acsA32[a]
                        + (size_t)(row0 + row) * C_ + c4 * 4);
            *(uint2*)(X0w + row * 52 + a * 8 + c4 * 2) = cvt4h(v);
        }
    };
    // buf1: enc[48..127], 10 chunks/row, 1280 chunks, 5 iters
    auto stage_buf1 = [&](int row0) {
#pragma unroll
        for (int it = 0; it < 5; it++) {
            int idx = it * 256 + tid;
            int row = idx / 10, u = idx - (idx / 10) * 10;
            const void* src = g_ench + (size_t)(row0 + row) * D_ + 48 + u * 8;
            cpasync16(x1b + (uint32_t)(row * 44 + u * 4) * 4, src);
        }
        CPCOMMIT();
    };

    stage_buf0(tb * 128);
    stage_buf1(tb * 128);

    const uint2* Wq = (const uint2*)(smf + WP_OFF);    // u64 view
    const int nb = (wc >> 4) * 8 + g;                  // u64 col base

    // ldmatrix lane addressing (A fragments)
    const int lrow = ((lane >> 3) & 1) * 8 + (lane & 7);
    const uint32_t lk16 = (uint32_t)(lane >> 4) * 16;  // byte offset for k8-15
    const uint32_t aX0base = x0b + (uint32_t)((wr + lrow) * 208) + lk16;
    const uint32_t aX1base = x1b + (uint32_t)((wr + lrow) * 176) + lk16;

    for (int tt = tb; tt < te; tt++) {
        const int row0 = tt * 128;
        const bool hasNext = (tt + 1 < te);
        float acc[2][8][4];
#pragma unroll
        for (int mi = 0; mi < 2; mi++)
#pragma unroll
            for (int ni = 0; ni < 8; ni++)
#pragma unroll
                for (int e = 0; e < 4; e++) acc[mi][ni][e] = 0.f;

        // ---- half 0: ks 0..5 ----
        CPWAITG(1);
        __syncthreads();
#pragma unroll
        for (int ks = 0; ks < 6; ks++) {
            uint32_t a[2][4];
            ldsm_x4(a[0][0], a[0][1], a[0][2], a[0][3], aX0base + ks * 32);
            ldsm_x4(a[1][0], a[1][1], a[1][2], a[1][3],
                    aX0base + 16 * 208 + ks * 32);
            const int kr0 = (ks * 8 + t) * 68 + nb;
            uint2 c0v[4], c1v[4];
#pragma unroll
            for (int j = 0; j < 4; j++) {
                c0v[j] = Wq[kr0 + j * 8];
                c1v[j] = Wq[kr0 + 4 * 68 + j * 8];
            }
#pragma unroll
            for (int mi = 0; mi < 2; mi++)
#pragma unroll
                for (int j = 0; j < 4; j++) {
                    mma16(acc[mi][2 * j],     a[mi], c0v[j].x, c1v[j].x);
                    mma16(acc[mi][2 * j + 1], a[mi], c0v[j].y, c1v[j].y);
                }
        }
        __syncthreads();
        if (hasNext) stage_buf0((tt + 1) * 128);

        // per-warp argmax: lane owns row wr+lane (fp32 acs)
        int myc;
        {
            const float* ar = acsSelf + (size_t)(row0 + wr + lane) * C_;
            float4 v0 = *(const float4*)ar;
            float4 v1 = *(const float4*)(ar + 4);
            float4 v2 = *(const float4*)(ar + 8);
            float4 v3 = *(const float4*)(ar + 12);
            float vv[16] = {v0.x,v0.y,v0.z,v0.w, v1.x,v1.y,v1.z,v1.w,
                            v2.x,v2.y,v2.z,v2.w, v3.x,v3.y,v3.z,v3.w};
            float best = vv[0]; myc = 0;
#pragma unroll
            for (int cc = 1; cc < C_; cc++)
                if (vv[cc] > best) { best = vv[cc]; myc = cc; }
        }

        // ---- half 1: ks 6..10 ----
        if (hasNext) { CPWAITG(1); } else { CPWAITG(0); }
        __syncthreads();
#pragma unroll
        for (int ks = 6; ks < 11; ks++) {
            uint32_t a[2][4];
            ldsm_x4(a[0][0], a[0][1], a[0][2], a[0][3],
                    aX1base + (ks - 6) * 32);
            ldsm_x4(a[1][0], a[1][1], a[1][2], a[1][3],
                    aX1base + 16 * 176 + (ks - 6) * 32);
            const int kr0 = (ks * 8 + t) * 68 + nb;
            uint2 c0v[4], c1v[4];
#pragma unroll
            for (int j = 0; j < 4; j++) {
                c0v[j] = Wq[kr0 + j * 8];
                c1v[j] = Wq[kr0 + 4 * 68 + j * 8];
            }
#pragma unroll
            for (int mi = 0; mi < 2; mi++)
#pragma unroll
                for (int j = 0; j < 4; j++) {
                    mma16(acc[mi][2 * j],     a[mi], c0v[j].x, c1v[j].x);
                    mma16(acc[mi][2 * j + 1], a[mi], c0v[j].y, c1v[j].y);
                }
        }
        __syncthreads();       // buf1 consumed
        if (hasNext) stage_buf1((tt + 1) * 128);

        // ---- epilogue: relu(acc+b1) . W2[:,c]; two commutative atomics ----
#pragma unroll
        for (int mi = 0; mi < 2; mi++) {
            int r0 = wr + mi * 16 + g;
            int cR0 = __shfl_sync(0xffffffffu, myc, mi * 16 + g);
            int cR1 = __shfl_sync(0xffffffffu, myc, mi * 16 + g + 8);
            float s0 = 0.f, s1 = 0.f;
#pragma unroll
            for (int ni = 0; ni < 8; ni++) {
                int col0 = wc + ni * 8 + 2 * t;
                float bb0 = smf[B1_OFF + col0], bb1 = smf[B1_OFF + col0 + 1];
                float w00 = smf[W2_OFF + col0 * 17 + cR0];
                float w01 = smf[W2_OFF + (col0 + 1) * 17 + cR0];
                float w10 = smf[W2_OFF + col0 * 17 + cR1];
                float w11 = smf[W2_OFF + (col0 + 1) * 17 + cR1];
                s0 += fmaxf(acc[mi][ni][0] + bb0, 0.f) * w00
                    + fmaxf(acc[mi][ni][1] + bb1, 0.f) * w01;
                s1 += fmaxf(acc[mi][ni][2] + bb0, 0.f) * w10
                    + fmaxf(acc[mi][ni][3] + bb1, 0.f) * w11;
            }
            s0 += __shfl_xor_sync(0xffffffffu, s0, 1);
            s0 += __shfl_xor_sync(0xffffffffu, s0, 2);
            s1 += __shfl_xor_sync(0xffffffffu, s1, 1);
            s1 += __shfl_xor_sync(0xffffffffu, s1, 2);
            if (t == 0) {
                if (wn == 0) { s0 += smf[B2_OFF + cR0]; s1 += smf[B2_OFF + cR1]; }
                atomicAdd(&outp[row0 + r0], s0);
                atomicAdd(&outp[row0 + r0 + 8], s1);
            }
        }
    }
}

// ---------------------------------------------------------------------------
extern "C" void kernel_launch(void* const* d_in, const int* in_sizes, int n_in,
                              void* d_out, int out_size)
{
    const float* state = (const float*)d_in[0];
    const float* acs   = (const float*)d_in[1];
    const float* encW  = (const float*)d_in[2];
    const float* encb  = (const float*)d_in[3];
    const float* eW1   = (const float*)d_in[4];
    const float* eb1   = (const float*)d_in[5];
    const float* eW2   = (const float*)d_in[6];
    const float* eb2   = (const float*)d_in[7];
    const float* iW1   = (const float*)d_in[8];
    const float* ib1   = (const float*)d_in[9];
    const float* iW2   = (const float*)d_in[10];
    const float* ib2   = (const float*)d_in[11];
    float* out = (float*)d_out;

    const int B = in_sizes[0] / S_;          // 32768

    cudaFuncSetAttribute(enc_kernel,
        cudaFuncAttributeMaxDynamicSharedMemorySize, E_SMEMB);
    cudaFuncSetAttribute(critic_kernel,
        cudaFuncAttributeMaxDynamicSharedMemorySize, K_SMEMB);

    enc_kernel<<<B / 64 / NTE, 256, E_SMEMB>>>(state, encW, encb, B);

    critic_kernel<<<NCTA, 256, K_SMEMB>>>(acs, eW1, eb1, eW2, eb2,
                                          iW1, ib1, iW2, ib2, out, B);
}

// round 16
// speedup vs baseline: 1.1157x; 1.1157x over previous
#include <cuda_runtime.h>
#include <cuda_fp16.h>
#include <cstdint>

// ---------------------------------------------------------------------------
// CentralCritic, both GEMMs on fp16 mma.sync.m16n8k16 (f32 accumulate).
// R16 = R14 (best-known components) + globally balanced critic partition:
//   flat 5120-tile space split linearly over 296 CTAs (17-18 tiles each,
//   max straggler 18 vs old 19), segments re-stage W when crossing a pair.
// ---------------------------------------------------------------------------

#define A_   4
#define H_   3
#define HI_  2
#define C_   16
#define S_   256
#define D_   128
#define IN_  176
#define NPAIR 20
#define NCTA  296    // critic CTAs: exactly 1 resident wave (2 CTAs/SM x 148)
#define NTE   2      // 64-row tiles per enc CTA -> 256 enc CTAs

// critic smem layout (u32 offsets)
#define WP_OFF   0                       // 88 k2-rows * 136 u32 = 11968
#define X0_OFF   11968                   // 128*52 u32 = 6656
#define X1_OFF   18624                   // 128*44 u32 = 5632
#define W2_OFF   24256                   // 128*17 = 2176
#define B1_OFF   26432                   // 128
#define B2_OFF   26560                   // 16
#define K_SMEMB  (26704 * 4)             // 106816 B (x2 CTA <= 228KB)

// enc smem layout (u32 offsets)
#define EW_OFF   0                       // 128 k2-rows * 136 u32 = 17408
#define EX_OFF   17408                   // 64 rows * 132 u32 = 8448
#define EB_OFF   25856                   // 128 floats
#define E_SMEMB  (25984 * 4)             // 103936 B (x2 CTA <= 228KB)

__device__ __half g_ench[32768 * D_];            // enc activations, fp16
__device__ __half g_acsh[A_ * H_ * 32768 * C_];  // acs, fp16 (GEMM operand)

__constant__ int c_loo[4][3] = {{1,2,3},{0,2,3},{0,1,3},{0,1,2}};

// ---- helpers ---------------------------------------------------------------
__device__ __forceinline__ uint32_t smem_u32(const void* p) {
    uint32_t r;
    asm("{ .reg .u64 t; cvta.to.shared.u64 t, %1; cvt.u32.u64 %0, t; }"
        : "=r"(r) : "l"(p));
    return r;
}
__device__ __forceinline__ void cpasync16(uint32_t dst, const void* src) {
    asm volatile("cp.async.cg.shared.global [%0], [%1], 16;"
                 :: "r"(dst), "l"(src));
}
#define CPCOMMIT()  asm volatile("cp.async.commit_group;" ::: "memory")
#define CPWAITG(n)  asm volatile("cp.async.wait_group %0;" :: "n"(n) : "memory")

__device__ __forceinline__ void ldsm_x4(uint32_t& r0, uint32_t& r1,
                                        uint32_t& r2, uint32_t& r3,
                                        uint32_t addr) {
    asm volatile("ldmatrix.sync.aligned.m8n8.x4.shared.b16 {%0,%1,%2,%3}, [%4];"
                 : "=r"(r0), "=r"(r1), "=r"(r2), "=r"(r3) : "r"(addr));
}
// fp16 k16
__device__ __forceinline__ void mma16(float* d, const uint32_t* a,
                                      uint32_t b0, uint32_t b1) {
    asm volatile(
        "mma.sync.aligned.m16n8k16.row.col.f32.f16.f16.f32 "
        "{%0,%1,%2,%3}, {%4,%5,%6,%7}, {%8,%9}, {%0,%1,%2,%3};"
        : "+f"(d[0]), "+f"(d[1]), "+f"(d[2]), "+f"(d[3])
        : "r"(a[0]), "r"(a[1]), "r"(a[2]), "r"(a[3]), "r"(b0), "r"(b1));
}
__device__ __forceinline__ uint2 cvt4h(float4 v) {
    __half2 h0 = __floats2half2_rn(v.x, v.y);
    __half2 h1 = __floats2half2_rn(v.z, v.w);
    uint2 o; o.x = *(uint32_t*)&h0; o.y = *(uint32_t*)&h1;
    return o;
}

// ---------------------------------------------------------------------------
// encoder: zero d_out + acs->fp16 prologue, then
//          relu(state @ encW + b) -> g_ench (fp16), fp16 m16n8k16 GEMM.
// ---------------------------------------------------------------------------
__global__ __launch_bounds__(256, 2) void enc_kernel(
    const float* __restrict__ state, const float* __restrict__ encW,
    const float* __restrict__ encb, const float* __restrict__ acs,
    float* __restrict__ outz, int B)
{
    extern __shared__ float smf[];
    const int tid = threadIdx.x, wid = tid >> 5, lane = tid & 31;
    const int g = lane >> 2, t = lane & 3;
    const int wm = wid >> 1, wn = wid & 1;
    const int wr = wm * 16, wc = wn * 64;
    const int gthr = blockIdx.x * 256 + tid;
    const int nthr = gridDim.x * 256;

    // ---- zero d_out (atomic epilogue accumulates into it) ----
    {
        const int n4 = (A_ * H_ + A_ * HI_) * B / 4;
        float4 z = make_float4(0.f, 0.f, 0.f, 0.f);
        for (int idx = gthr; idx < n4; idx += nthr)
            *(float4*)(outz + (size_t)idx * 4) = z;
    }
    // ---- acs fp32 -> fp16 (layout preserved) ----
    {
        const int n4 = A_ * H_ * B * C_ / 4;
        for (int idx = gthr; idx < n4; idx += nthr) {
            float4 v = *(const float4*)(acs + (size_t)idx * 4);
            *(uint2*)(g_acsh + (size_t)idx * 4) = cvt4h(v);
        }
    }

    // ---- stage encW fp16, (n, n+8)-interleaved u64 rows ----
    __half* Wph = (__half*)(smf + EW_OFF);
    for (int it = 0; it < 32; it++) {
        int fi = it * 256 + tid;            // 8192 float4 (256 k x 32 n4)
        int k = fi >> 5, n0 = (fi & 31) * 4;
        float4 v = *(const float4*)(encW + (size_t)k * D_ + n0);
        int base = (k >> 1) * 272 + (n0 >> 4) * 32 + ((n0 >> 3) & 1) * 2
                 + (k & 1) + (n0 & 7) * 4;
        Wph[base + 0]  = __float2half_rn(v.x);
        Wph[base + 4]  = __float2half_rn(v.y);
        Wph[base + 8]  = __float2half_rn(v.z);
        Wph[base + 12] = __float2half_rn(v.w);
    }
    if (tid < D_) smf[EB_OFF + tid] = encb[tid];
    __syncthreads();

    const uint32_t xb = smem_u32(smf + EX_OFF);
    const uint2* Wq = (const uint2*)(smf + EW_OFF);
    const int nb = wn * 32 + g;                        // u64 col base
    const int lrow = ((lane >> 3) & 1) * 8 + (lane & 7);
    const uint32_t lk16 = (uint32_t)(lane >> 4) * 16;
    const uint32_t aXbase = xb + (uint32_t)((wr + lrow) * 528) + lk16;

    for (int tt = 0; tt < NTE; tt++) {
        const int row0 = (blockIdx.x * NTE + tt) * 64;

        // ---- stage X: 64 rows x 256 fp32 -> fp16, row stride 132 u32 ----
        uint32_t* Xu = (uint32_t*)(smf + EX_OFF);
        for (int it = 0; it < 16; it++) {
            int idx = it * 256 + tid;
            int row = idx >> 6, c0 = idx & 63;
            float4 v = *(const float4*)(state + (size_t)(row0 + row) * S_ + c0 * 4);
            *(uint2*)(Xu + row * 132 + c0 * 2) = cvt4h(v);
        }
        __syncthreads();

        float acc[8][4];
#pragma unroll
        for (int ni = 0; ni < 8; ni++)
#pragma unroll
            for (int e = 0; e < 4; e++) acc[ni][e] = 0.f;

#pragma unroll
        for (int ks = 0; ks < 16; ks++) {
            uint32_t a[4];
            ldsm_x4(a[0], a[1], a[2], a[3], aXbase + ks * 32);
            const int kr0 = (ks * 8 + t) * 68 + nb;
            uint2 c0v[4], c1v[4];
#pragma unroll
            for (int j = 0; j < 4; j++) {
                c0v[j] = Wq[kr0 + j * 8];
                c1v[j] = Wq[kr0 + 4 * 68 + j * 8];
            }
#pragma unroll
            for (int j = 0; j < 4; j++) {
                mma16(acc[2 * j],     a, c0v[j].x, c1v[j].x);
                mma16(acc[2 * j + 1], a, c0v[j].y, c1v[j].y);
            }
        }
        __syncthreads();

        // ---- epilogue: bias + relu -> g_ench fp16 ----
        int r0 = row0 + wr + g;
#pragma unroll
        for (int ni = 0; ni < 8; ni++) {
            int col = wc + ni * 8 + 2 * t;
            float b0 = smf[EB_OFF + col], b1v = smf[EB_OFF + col + 1];
            __half2 h0 = __floats2half2_rn(fmaxf(acc[ni][0] + b0, 0.f),
                                           fmaxf(acc[ni][1] + b1v, 0.f));
            __half2 h1 = __floats2half2_rn(fmaxf(acc[ni][2] + b0, 0.f),
                                           fmaxf(acc[ni][3] + b1v, 0.f));
            *(__half2*)(g_ench + (size_t)r0 * D_ + col) = h0;
            *(__half2*)(g_ench + (size_t)(r0 + 8) * D_ + col) = h1;
        }
    }
}

// ---------------------------------------------------------------------------
// critic: 256 thr, 8 warps (4 wm x 2 wn), warp tile 32x64, fp16 m16n8k16,
// 2 CTAs/SM (single wave), ldmatrix A-feeds, u64-interleaved W, shfl argmax,
// atomic 2-partial epilogue. Globally balanced: flat tile ids [0, 20*tilesT)
// split linearly; per-pair segments re-stage weights on pair crossings.
// ---------------------------------------------------------------------------
__global__ __launch_bounds__(256, 2) void critic_kernel(
    const float* __restrict__ acs,
    const float* __restrict__ eW1, const float* __restrict__ eb1,
    const float* __restrict__ eW2, const float* __restrict__ eb2,
    const float* __restrict__ iW1, const float* __restrict__ ib1,
    const float* __restrict__ iW2, const float* __restrict__ ib2,
    float* __restrict__ out, int B)
{
    extern __shared__ float smf[];
    const int tid = threadIdx.x, wid = tid >> 5, lane = tid & 31;
    const int g = lane >> 2, t = lane & 3;
    const int wm = wid >> 1, wn = wid & 1;
    const int wr = wm * 32, wc = wn * 64;

    const int cb = blockIdx.x;
    const int tilesT = B / 128;                    // 256
    const long TT = (long)NPAIR * tilesT;          // 5120
    int tt       = (int)((long)cb * TT / NCTA);
    const int ge = (int)((long)(cb + 1) * TT / NCTA);

    const uint32_t x0b = smem_u32(smf + X0_OFF);
    const uint32_t x1b = smem_u32(smf + X1_OFF);
    const uint2* Wq = (const uint2*)(smf + WP_OFF);
    const int nb = (wc >> 4) * 8 + g;
    const int lrow = ((lane >> 3) & 1) * 8 + (lane & 7);
    const uint32_t lk16 = (uint32_t)(lane >> 4) * 16;
    const uint32_t aX0base = x0b + (uint32_t)((wr + lrow) * 208) + lk16;
    const uint32_t aX1base = x1b + (uint32_t)((wr + lrow) * 176) + lk16;

    while (tt < ge) {
        const int p = tt / tilesT;
        const int segEnd = min(ge, (p + 1) * tilesT);

        // ---- per-pair pointers ----
        int i, head;
        const float *W1, *b1, *W2, *b2;
        float* outp;
        if (p < A_ * H_) {
            i = p / H_; int j = p % H_; head = j;
            W1 = eW1 + (size_t)(j * A_ + i) * IN_ * D_;
            b1 = eb1 + (size_t)(j * A_ + i) * D_;
            W2 = eW2 + (size_t)(j * A_ + i) * D_ * C_;
            b2 = eb2 + (size_t)(j * A_ + i) * C_;
            outp = out + (size_t)p * B;
        } else {
            int q = p - A_ * H_;
            i = q / HI_; int j = q % HI_; head = j + 1;
            W1 = iW1 + (size_t)(j * A_ + i) * IN_ * D_;
            b1 = ib1 + (size_t)(j * A_ + i) * D_;
            W2 = iW2 + (size_t)(j * A_ + i) * D_ * C_;
            b2 = ib2 + (size_t)(j * A_ + i) * C_;
            outp = out + (size_t)(A_ * H_) * B + (size_t)q * B;
        }
        const __half* acsA[3];
        acsA[0] = g_acsh + (size_t)(c_loo[i][0] * H_ + head) * B * C_;
        acsA[1] = g_acsh + (size_t)(c_loo[i][1] * H_ + head) * B * C_;
        acsA[2] = g_acsh + (size_t)(c_loo[i][2] * H_ + head) * B * C_;
        const float* acsSelf = acs + (size_t)(i * H_ + head) * B * C_;

        __syncthreads();   // prior segment fully done with smem W/W2/b

        // ---- stage W1 fp16 interleaved, W2, b1, b2 ----
        __half* Wph = (__half*)(smf + WP_OFF);
        for (int it = 0; it < 22; it++) {
            int fi = it * 256 + tid;
            int k = fi >> 5, n0 = (fi & 31) * 4;
            float4 v = *(const float4*)(W1 + (size_t)k * D_ + n0);
            int base = (k >> 1) * 272 + (n0 >> 4) * 32 + ((n0 >> 3) & 1) * 2
                     + (k & 1) + (n0 & 7) * 4;
            Wph[base + 0]  = __float2half_rn(v.x);
            Wph[base + 4]  = __float2half_rn(v.y);
            Wph[base + 8]  = __float2half_rn(v.z);
            Wph[base + 12] = __float2half_rn(v.w);
        }
        for (int it = 0; it < 8; it++) {
            int idx = it * 256 + tid;
            int d = idx >> 4, c = idx & 15;
            smf[W2_OFF + d * 17 + c] = W2[idx];
        }
        if (tid < D_) smf[B1_OFF + tid] = b1[tid];
        if (tid < C_) smf[B2_OFF + tid] = b2[tid];

        // ---- staging lambdas (rows local to pair) ----
        auto stage_buf0 = [&](int row0) {
#pragma unroll
            for (int it = 0; it < 6; it++) {
                int idx = it * 256 + tid;
                int row = idx / 12, c = idx - (idx / 12) * 12;
                const void* src;
                if (c < 6)
                    src = acsA[c >> 1] + (size_t)(row0 + row) * C_ + (c & 1) * 8;
                else
                    src = g_ench + (size_t)(row0 + row) * D_ + (c - 6) * 8;
                cpasync16(x0b + (uint32_t)(row * 52 + c * 4) * 4, src);
            }
            CPCOMMIT();
        };
        auto stage_buf1 = [&](int row0) {
#pragma unroll
            for (int it = 0; it < 5; it++) {
                int idx = it * 256 + tid;
                int row = idx / 10, u = idx - (idx / 10) * 10;
                const void* src = g_ench + (size_t)(row0 + row) * D_ + 48 + u * 8;
                cpasync16(x1b + (uint32_t)(row * 44 + u * 4) * 4, src);
            }
            CPCOMMIT();
        };

        const int lt0 = (tt - p * tilesT) * 128;
        stage_buf0(lt0);
        stage_buf1(lt0);

        for (; tt < segEnd; tt++) {
            const int row0 = (tt - p * tilesT) * 128;
            const bool hasNext = (tt + 1 < segEnd);
            float acc[2][8][4];
#pragma unroll
            for (int mi = 0; mi < 2; mi++)
#pragma unroll
                for (int ni = 0; ni < 8; ni++)
#pragma unroll
                    for (int e = 0; e < 4; e++) acc[mi][ni][e] = 0.f;

            // ---- half 0: ks 0..5 ----
            CPWAITG(1);
            __syncthreads();
#pragma unroll
            for (int ks = 0; ks < 6; ks++) {
                uint32_t a[2][4];
                ldsm_x4(a[0][0], a[0][1], a[0][2], a[0][3], aX0base + ks * 32);
                ldsm_x4(a[1][0], a[1][1], a[1][2], a[1][3],
                        aX0base + 16 * 208 + ks * 32);
                const int kr0 = (ks * 8 + t) * 68 + nb;
                uint2 c0v[4], c1v[4];
#pragma unroll
                for (int j = 0; j < 4; j++) {
                    c0v[j] = Wq[kr0 + j * 8];
                    c1v[j] = Wq[kr0 + 4 * 68 + j * 8];
                }
#pragma unroll
                for (int mi = 0; mi < 2; mi++)
#pragma unroll
                    for (int j = 0; j < 4; j++) {
                        mma16(acc[mi][2 * j],     a[mi], c0v[j].x, c1v[j].x);
                        mma16(acc[mi][2 * j + 1], a[mi], c0v[j].y, c1v[j].y);
                    }
            }
            __syncthreads();
            if (hasNext) stage_buf0(row0 + 128);

            // per-warp argmax: lane owns row wr+lane (fp32 acs)
            int myc;
            {
                const float* ar = acsSelf + (size_t)(row0 + wr + lane) * C_;
                float4 v0 = *(const float4*)ar;
                float4 v1 = *(const float4*)(ar + 4);
                float4 v2 = *(const float4*)(ar + 8);
                float4 v3 = *(const float4*)(ar + 12);
                float vv[16] = {v0.x,v0.y,v0.z,v0.w, v1.x,v1.y,v1.z,v1.w,
                                v2.x,v2.y,v2.z,v2.w, v3.x,v3.y,v3.z,v3.w};
                float best = vv[0]; myc = 0;
#pragma unroll
                for (int cc = 1; cc < C_; cc++)
                    if (vv[cc] > best) { best = vv[cc]; myc = cc; }
            }

            // ---- half 1: ks 6..10 ----
            if (hasNext) { CPWAITG(1); } else { CPWAITG(0); }
            __syncthreads();
#pragma unroll
            for (int ks = 6; ks < 11; ks++) {
                uint32_t a[2][4];
                ldsm_x4(a[0][0], a[0][1], a[0][2], a[0][3],
                        aX1base + (ks - 6) * 32);
                ldsm_x4(a[1][0], a[1][1], a[1][2], a[1][3],
                        aX1base + 16 * 176 + (ks - 6) * 32);
                const int kr0 = (ks * 8 + t) * 68 + nb;
                uint2 c0v[4], c1v[4];
#pragma unroll
                for (int j = 0; j < 4; j++) {
                    c0v[j] = Wq[kr0 + j * 8];
                    c1v[j] = Wq[kr0 + 4 * 68 + j * 8];
                }
#pragma unroll
                for (int mi = 0; mi < 2; mi++)
#pragma unroll
                    for (int j = 0; j < 4; j++) {
                        mma16(acc[mi][2 * j],     a[mi], c0v[j].x, c1v[j].x);
                        mma16(acc[mi][2 * j + 1], a[mi], c0v[j].y, c1v[j].y);
                    }
            }
            __syncthreads();
            if (hasNext) stage_buf1(row0 + 128);

            // ---- epilogue ----
#pragma unroll
            for (int mi = 0; mi < 2; mi++) {
                int r0 = wr + mi * 16 + g;
                int cR0 = __shfl_sync(0xffffffffu, myc, mi * 16 + g);
                int cR1 = __shfl_sync(0xffffffffu, myc, mi * 16 + g + 8);
                float s0 = 0.f, s1 = 0.f;
#pragma unroll
                for (int ni = 0; ni < 8; ni++) {
                    int col0 = wc + ni * 8 + 2 * t;
                    float bb0 = smf[B1_OFF + col0], bb1 = smf[B1_OFF + col0 + 1];
                    float w00 = smf[W2_OFF + col0 * 17 + cR0];
                    float w01 = smf[W2_OFF + (col0 + 1) * 17 + cR0];
                    float w10 = smf[W2_OFF + col0 * 17 + cR1];
                    float w11 = smf[W2_OFF + (col0 + 1) * 17 + cR1];
                    s0 += fmaxf(acc[mi][ni][0] + bb0, 0.f) * w00
                        + fmaxf(acc[mi][ni][1] + bb1, 0.f) * w01;
                    s1 += fmaxf(acc[mi][ni][2] + bb0, 0.f) * w10
                        + fmaxf(acc[mi][ni][3] + bb1, 0.f) * w11;
                }
                s0 += __shfl_xor_sync(0xffffffffu, s0, 1);
                s0 += __shfl_xor_sync(0xffffffffu, s0, 2);
                s1 += __shfl_xor_sync(0xffffffffu, s1, 1);
                s1 += __shfl_xor_sync(0xffffffffu, s1, 2);
                if (t == 0) {
                    if (wn == 0) { s0 += smf[B2_OFF + cR0];
                                   s1 += smf[B2_OFF + cR1]; }
                    atomicAdd(&outp[row0 + r0], s0);
                    atomicAdd(&outp[row0 + r0 + 8], s1);
                }
            }
        }
    }
}

// ---------------------------------------------------------------------------
extern "C" void kernel_launch(void* const* d_in, const int* in_sizes, int n_in,
                              void* d_out, int out_size)
{
    const float* state = (const float*)d_in[0];
    const float* acs   = (const float*)d_in[1];
    const float* encW  = (const float*)d_in[2];
    const float* encb  = (const float*)d_in[3];
    const float* eW1   = (const float*)d_in[4];
    const float* eb1   = (const float*)d_in[5];
    const float* eW2   = (const float*)d_in[6];
    const float* eb2   = (const float*)d_in[7];
    const float* iW1   = (const float*)d_in[8];
    const float* ib1   = (const float*)d_in[9];
    const float* iW2   = (const float*)d_in[10];
    const float* ib2   = (const float*)d_in[11];
    float* out = (float*)d_out;

    const int B = in_sizes[0] / S_;          // 32768

    cudaFuncSetAttribute(enc_kernel,
        cudaFuncAttributeMaxDynamicSharedMemorySize, E_SMEMB);
    cudaFuncSetAttribute(critic_kernel,
        cudaFuncAttributeMaxDynamicSharedMemorySize, K_SMEMB);

    enc_kernel<<<B / 64 / NTE, 256, E_SMEMB>>>(state, encW, encb, acs, out, B);

    critic_kernel<<<NCTA, 256, K_SMEMB>>>(acs, eW1, eb1, eW2, eb2,
                                          iW1, ib1, iW2, ib2, out, B);
}